// round 7
// baseline (speedup 1.0000x reference)
#include <cuda_runtime.h>
#include <cuda_bf16.h>
#include <math.h>
#include <stdint.h>

#define DB 2
#define DC 8
#define DN 16384
#define DD 256
#define DH 64
#define DW 64
#define ROWS (DB*DN)

// ---------------- scratch ----------------
__device__ __align__(256) __nv_bfloat16 g_qn_h [ROWS*DD];
__device__ __align__(256) __nv_bfloat16 g_qn_l [ROWS*DD];
__device__ __align__(256) float         g_qt   [ROWS*DD];
__device__ __align__(256) __nv_bfloat16 g_sb_h [ROWS*DD];
__device__ __align__(256) __nv_bfloat16 g_sb_l [ROWS*DD];
__device__ float g_qbk [ROWS];
__device__ float g_asum[ROWS];
__device__ __align__(256) float g_WqT [DD*DD];
__device__ __align__(256) float g_WoT [DD*DD];
__device__ __align__(256) float g_WvT [DD*DD];
__device__ __align__(256) float g_WkT [DD*DD];
__device__ __align__(256) __nv_bfloat16 g_MT_h [DD*DD];
__device__ __align__(256) __nv_bfloat16 g_MT_l [DD*DD];
__device__ __align__(256) __nv_bfloat16 g_W2T_h[DD*DD];
__device__ __align__(256) __nv_bfloat16 g_W2T_l[DD*DD];
__device__ float g_v1 [DD];
__device__ float g_u  [DD];
__device__ float g_wb2[DD];
__device__ float g_c0;

__device__ __forceinline__ float4 ld4(const float* p) { return *(const float4*)p; }

__device__ __forceinline__ void bsplit(float x, __nv_bfloat16& h, __nv_bfloat16& l) {
    h = __float2bfloat16_rn(x);
    l = __float2bfloat16_rn(x - __bfloat162float(h));
}
__device__ __forceinline__ unsigned pk(__nv_bfloat16 a, __nv_bfloat16 b) {
    unsigned short x = *(unsigned short*)&a, y = *(unsigned short*)&b;
    return (unsigned)x | ((unsigned)y << 16);
}

__device__ __forceinline__ uint32_t smem_u32(const void* p) {
    uint32_t a;
    asm("{ .reg .u64 t; cvta.to.shared.u64 t, %1; cvt.u32.u64 %0, t; }" : "=r"(a) : "l"(p));
    return a;
}
__device__ __forceinline__ void cpa16(uint32_t d, const void* s) {
    asm volatile("cp.async.cg.shared.global [%0], [%1], 16;" :: "r"(d), "l"(s));
}

#define LDM4(r, addr) \
    asm volatile("ldmatrix.sync.aligned.m8n8.x4.shared.b16 {%0,%1,%2,%3}, [%4];" \
        : "=r"((r)[0]), "=r"((r)[1]), "=r"((r)[2]), "=r"((r)[3]) : "r"(addr))

#define MMAB(d, a, b0, b1) \
    asm volatile("mma.sync.aligned.m16n8k16.row.col.f32.bf16.bf16.f32 " \
        "{%0,%1,%2,%3}, {%4,%5,%6,%7}, {%8,%9}, {%0,%1,%2,%3};" \
        : "+f"((d)[0]), "+f"((d)[1]), "+f"((d)[2]), "+f"((d)[3]) \
        : "r"((a)[0]), "r"((a)[1]), "r"((a)[2]), "r"((a)[3]), "r"(b0), "r"(b1))

// ---------------- transposes ----------------
__global__ void k_tr(const float* __restrict__ Wq, const float* __restrict__ Wo,
                     const float* __restrict__ Wkv)
{
    __shared__ float t[32][33];
    int z = blockIdx.z;
    const float* src; int ld, off; float* dst;
    if      (z == 0) { src = Wq;  ld = 256; off = 0;   dst = g_WqT; }
    else if (z == 1) { src = Wo;  ld = 256; off = 0;   dst = g_WoT; }
    else if (z == 2) { src = Wkv; ld = 512; off = 256; dst = g_WvT; }
    else             { src = Wkv; ld = 512; off = 0;   dst = g_WkT; }
    int bx = blockIdx.x*32, by = blockIdx.y*32;
    for (int yy = threadIdx.y; yy < 32; yy += 8)
        t[yy][threadIdx.x] = src[(size_t)(by+yy)*ld + off + bx + threadIdx.x];
    __syncthreads();
    for (int yy = threadIdx.y; yy < 32; yy += 8)
        dst[(size_t)(bx+yy)*256 + by + threadIdx.x] = t[threadIdx.x][yy];
}

// ---------------- small vectors ----------------
__global__ void k_vec(const float* __restrict__ bq, const float* __restrict__ bkv,
                      const float* __restrict__ Wo)
{
    int which = blockIdx.x, t = threadIdx.x;
    __shared__ float v[256];
    if      (which == 0) v[t] = bkv[t];
    else if (which == 1) v[t] = bq[t];
    else                 v[t] = bkv[256 + t];
    __syncthreads();
    float acc = 0.f;
    if (which == 0) {
        for (int d = 0; d < 256; d++) acc += g_WqT[d*256 + t] * v[d];
        g_u[t] = acc;
        if (t == 0) { float c = 0.f; for (int d = 0; d < 256; d++) c += bq[d]*bkv[d]; g_c0 = c; }
    } else if (which == 1) {
        for (int d = 0; d < 256; d++) acc += g_WkT[d*256 + t] * v[d];
        g_v1[t] = acc;
    } else {
        for (int f = 0; f < 256; f++) acc += Wo[f*256 + t] * v[f];
        g_wb2[t] = acc;
    }
}

// ---------------- MT[f][e] = Wk@Wq^T ; W2T[t][f] = (Wv@Wo)^T, emit bf16 hi/lo ----------------
__global__ __launch_bounds__(256) void k_pre(const float* __restrict__ Wkv)
{
    __shared__ float Ar[8][256];
    int r0 = blockIdx.x * 8;
    const float* Bsrc; __nv_bfloat16 *Ch, *Cl;
    if (blockIdx.y == 0) {
        for (int i = threadIdx.x; i < 8*256; i += 256) {
            int j = i >> 8, d = i & 255;
            Ar[j][d] = Wkv[(size_t)(r0+j)*512 + d];
        }
        Bsrc = g_WqT; Ch = g_MT_h; Cl = g_MT_l;
    } else {
        for (int i = threadIdx.x; i < 8*256; i += 256) {
            int j = i >> 8, d = i & 255;
            Ar[j][d] = g_WoT[(size_t)(r0+j)*256 + d];
        }
        Bsrc = g_WvT; Ch = g_W2T_h; Cl = g_W2T_l;
    }
    __syncthreads();
    int e = threadIdx.x;
    float acc[8];
#pragma unroll
    for (int j = 0; j < 8; j++) acc[j] = 0.f;
    for (int d = 0; d < 256; d++) {
        float b = Bsrc[(size_t)d*256 + e];
#pragma unroll
        for (int j = 0; j < 8; j++) acc[j] += Ar[j][d] * b;
    }
#pragma unroll
    for (int j = 0; j < 8; j++) {
        __nv_bfloat16 h, l; bsplit(acc[j], h, l);
        Ch[(size_t)(r0+j)*256 + e] = h;
        Cl[(size_t)(r0+j)*256 + e] = l;
    }
}

// ---------------- layernorm + qbk, emits bf16 hi/lo ----------------
__global__ __launch_bounds__(256) void k_ln(const float* __restrict__ q,
                                            const float* __restrict__ gamma,
                                            const float* __restrict__ beta)
{
    int gw   = (blockIdx.x*256 + threadIdx.x) >> 5;
    int lane = threadIdx.x & 31;
    const float* row = q + (size_t)gw*DD;
    float4 x0 = ld4(row + lane*4);
    float4 x1 = ld4(row + 128 + lane*4);
    float s  = x0.x+x0.y+x0.z+x0.w + x1.x+x1.y+x1.z+x1.w;
    float ss = x0.x*x0.x+x0.y*x0.y+x0.z*x0.z+x0.w*x0.w
             + x1.x*x1.x+x1.y*x1.y+x1.z*x1.z+x1.w*x1.w;
#pragma unroll
    for (int off = 16; off; off >>= 1) {
        s  += __shfl_xor_sync(0xffffffffu, s,  off);
        ss += __shfl_xor_sync(0xffffffffu, ss, off);
    }
    float mu   = s * (1.f/DD);
    float var  = ss * (1.f/DD) - mu*mu;
    float rstd = rsqrtf(var + 1e-5f);
    float4 gm0 = ld4(gamma + lane*4), gm1 = ld4(gamma + 128 + lane*4);
    float4 bt0 = ld4(beta  + lane*4), bt1 = ld4(beta  + 128 + lane*4);
    float y[8];
    y[0] = (x0.x-mu)*rstd*gm0.x + bt0.x;  y[1] = (x0.y-mu)*rstd*gm0.y + bt0.y;
    y[2] = (x0.z-mu)*rstd*gm0.z + bt0.z;  y[3] = (x0.w-mu)*rstd*gm0.w + bt0.w;
    y[4] = (x1.x-mu)*rstd*gm1.x + bt1.x;  y[5] = (x1.y-mu)*rstd*gm1.y + bt1.y;
    y[6] = (x1.z-mu)*rstd*gm1.z + bt1.z;  y[7] = (x1.w-mu)*rstd*gm1.w + bt1.w;

    __nv_bfloat16 h[8], l[8];
#pragma unroll
    for (int i = 0; i < 8; i++) bsplit(y[i], h[i], l[i]);
    size_t base = (size_t)gw*DD;
    *(uint2*)(g_qn_h + base + lane*4)       = make_uint2(pk(h[0],h[1]), pk(h[2],h[3]));
    *(uint2*)(g_qn_h + base + 128 + lane*4) = make_uint2(pk(h[4],h[5]), pk(h[6],h[7]));
    *(uint2*)(g_qn_l + base + lane*4)       = make_uint2(pk(l[0],l[1]), pk(l[2],l[3]));
    *(uint2*)(g_qn_l + base + 128 + lane*4) = make_uint2(pk(l[4],l[5]), pk(l[6],l[7]));

    float4 u0 = ld4(g_u + lane*4), u1 = ld4(g_u + 128 + lane*4);
    float p = y[0]*u0.x + y[1]*u0.y + y[2]*u0.z + y[3]*u0.w
            + y[4]*u1.x + y[5]*u1.y + y[6]*u1.z + y[7]*u1.w;
#pragma unroll
    for (int off = 16; off; off >>= 1) p += __shfl_xor_sync(0xffffffffu, p, off);
    if (lane == 0) g_qbk[gw] = p + g_c0;
}

// ================= bf16 3-split mma.sync GEMM with ldmatrix =================
#define NCH 8
#define RS 80
#define ARR_B 10240
#define STG_BYTES (4*ARR_B)
#define SMEM_MMA (3*STG_BYTES)

__device__ __forceinline__ void ld_stage(uint32_t base,
        const __nv_bfloat16* __restrict__ Ah, const __nv_bfloat16* __restrict__ Al,
        const __nv_bfloat16* __restrict__ Bh, const __nv_bfloat16* __restrict__ Bl,
        size_t m0, int n0, int kb, int tid)
{
    for (int i = tid; i < 512; i += 256) {
        int row = i >> 2, slot = i & 3;
        uint32_t off = row*RS + slot*16;
        size_t ga = (m0 + row)*256 + kb + slot*8;
        size_t gb = (size_t)(n0 + row)*256 + kb + slot*8;
        cpa16(base + off,           Ah + ga);
        cpa16(base + ARR_B + off,   Al + ga);
        cpa16(base + 2*ARR_B + off, Bh + gb);
        cpa16(base + 3*ARR_B + off, Bl + gb);
    }
    asm volatile("cp.async.commit_group;");
}

__global__ __launch_bounds__(256, 1) void k_mma(int mode, float* __restrict__ outp,
                                                const float* __restrict__ resid,
                                                const float* __restrict__ bo)
{
    const __nv_bfloat16 *Ah, *Al, *Bh, *Bl; float* C;
    if (mode == 2) { Ah = g_qn_h; Al = g_qn_l; Bh = g_MT_h;  Bl = g_MT_l;  C = g_qt; }
    else           { Ah = g_sb_h; Al = g_sb_l; Bh = g_W2T_h; Bl = g_W2T_l; C = outp; }

    extern __shared__ __align__(16) char smem[];
    uint32_t sb = smem_u32(smem);
    int tid = threadIdx.x, lane = tid & 31, wid = tid >> 5;
    int wm = wid >> 1, wn = wid & 1;
    int qr = lane >> 2, qc = lane & 3;
    size_t m0 = (size_t)blockIdx.y * 128;
    int n0 = blockIdx.x * 128;

    uint32_t offA[2][2], offB[4][2];
    {
        int arow = lane & 15, asel = lane >> 4;
        int brow = (lane & 7) + ((lane & 16) >> 1);
        int bsel = (lane >> 3) & 1;
#pragma unroll
        for (int ks = 0; ks < 2; ks++) {
#pragma unroll
            for (int mi = 0; mi < 2; mi++)
                offA[mi][ks] = (uint32_t)((wm*32 + mi*16 + arow)*RS + (2*ks + asel)*16);
#pragma unroll
            for (int nip = 0; nip < 4; nip++)
                offB[nip][ks] = (uint32_t)((wn*64 + nip*16 + brow)*RS + (2*ks + bsel)*16);
        }
    }

    float acc[2][8][4];
#pragma unroll
    for (int mi = 0; mi < 2; mi++)
#pragma unroll
        for (int ni = 0; ni < 8; ni++)
#pragma unroll
            for (int t = 0; t < 4; t++) acc[mi][ni][t] = 0.f;

    ld_stage(sb,             Ah, Al, Bh, Bl, m0, n0, 0,  tid);
    ld_stage(sb + STG_BYTES, Ah, Al, Bh, Bl, m0, n0, 32, tid);

    for (int s = 0; s < NCH; s++) {
        if (s == NCH - 1) asm volatile("cp.async.wait_group 0;");
        else              asm volatile("cp.async.wait_group 1;");
        __syncthreads();
        if (s + 2 < NCH)
            ld_stage(sb + ((s + 2) % 3)*STG_BYTES, Ah, Al, Bh, Bl, m0, n0, (s + 2)*32, tid);

        uint32_t st = sb + (s % 3)*STG_BYTES;
#pragma unroll
        for (int ks = 0; ks < 2; ks++) {
            unsigned ra[2][4], la[2][4], rb[4][4], lb[4][4];
#pragma unroll
            for (int mi = 0; mi < 2; mi++) {
                LDM4(ra[mi], st + offA[mi][ks]);
                LDM4(la[mi], st + ARR_B + offA[mi][ks]);
            }
#pragma unroll
            for (int nip = 0; nip < 4; nip++) {
                LDM4(rb[nip], st + 2*ARR_B + offB[nip][ks]);
                LDM4(lb[nip], st + 3*ARR_B + offB[nip][ks]);
            }
#pragma unroll
            for (int mi = 0; mi < 2; mi++)
#pragma unroll
                for (int ni = 0; ni < 8; ni++)
                    MMAB(acc[mi][ni], ra[mi], rb[ni>>1][(ni&1)*2], rb[ni>>1][(ni&1)*2+1]);
#pragma unroll
            for (int mi = 0; mi < 2; mi++)
#pragma unroll
                for (int ni = 0; ni < 8; ni++)
                    MMAB(acc[mi][ni], ra[mi], lb[ni>>1][(ni&1)*2], lb[ni>>1][(ni&1)*2+1]);
#pragma unroll
            for (int mi = 0; mi < 2; mi++)
#pragma unroll
                for (int ni = 0; ni < 8; ni++)
                    MMAB(acc[mi][ni], la[mi], rb[ni>>1][(ni&1)*2], rb[ni>>1][(ni&1)*2+1]);
        }
    }

#pragma unroll
    for (int mi = 0; mi < 2; mi++) {
        size_t r0 = m0 + wm*32 + mi*16 + qr;
        size_t r1 = r0 + 8;
        float as0 = 0.f, as1 = 0.f;
        if (mode == 3) { as0 = g_asum[r0]; as1 = g_asum[r1]; }
#pragma unroll
        for (int ni = 0; ni < 8; ni++) {
            int c = n0 + wn*64 + ni*8 + qc*2;
            float2 v0 = make_float2(acc[mi][ni][0], acc[mi][ni][1]);
            float2 v1 = make_float2(acc[mi][ni][2], acc[mi][ni][3]);
            if (mode == 2) {
                v0.x += g_v1[c]; v0.y += g_v1[c+1];
                v1.x += g_v1[c]; v1.y += g_v1[c+1];
            } else {
                float2 rs0 = *(const float2*)&resid[r0*256 + c];
                float2 rs1 = *(const float2*)&resid[r1*256 + c];
                float w0 = g_wb2[c], w1 = g_wb2[c+1];
                float b0 = bo[c], b1 = bo[c+1];
                v0.x += rs0.x + as0*w0 + b0;  v0.y += rs0.y + as0*w1 + b1;
                v1.x += rs1.x + as1*w0 + b0;  v1.y += rs1.y + as1*w1 + b1;
            }
            *(float2*)&C[r0*256 + c] = v0;
            *(float2*)&C[r1*256 + c] = v1;
        }
    }
}

// ============ fused gather+attention: one CTA (128 thr) per query, cp.async staging ============
__global__ __launch_bounds__(128) void k_attn(const float* __restrict__ feat,
                                              const float* __restrict__ coords,
                                              const int*   __restrict__ valid)
{
    __shared__ __align__(16) float sdata[DC*4*DD];  // 32 KB corner vectors
    __shared__ float    s_w[DC][4];
    __shared__ unsigned s_addr[DC][4];
    __shared__ int      s_vm[DC];
    __shared__ float    s_red[4*DC];

    int tid = threadIdx.x;
    int gw  = blockIdx.x;
    int b   = gw >> 14;
    int n   = gw & (DN - 1);
    uint32_t sb_data = smem_u32(sdata);

    if (tid < DC) {
        int c = tid;
        int ci = b*DC + c;
        int vmv = valid[(size_t)ci*DN + n];
        s_vm[c] = vmv;
        float2 xy = *((const float2*)coords + (size_t)ci*DN + n);
        float x = (xy.x + 1.0f)*0.5f*(float)(DW - 1);
        float y = (xy.y + 1.0f)*0.5f*(float)(DH - 1);
        float x0f = floorf(x), y0f = floorf(y);
        float wx = x - x0f, wy = y - y0f;
        int x0 = (int)x0f, y0 = (int)y0f;
        int x1 = x0 + 1,   y1 = y0 + 1;
        float w00 = (1.f-wy)*(1.f-wx), w01 = (1.f-wy)*wx;
        float w10 = wy*(1.f-wx),       w11 = wy*wx;
        bool bx0 = (unsigned)x0 < DW, bx1 = (unsigned)x1 < DW;
        bool by0 = (unsigned)y0 < DH, by1 = (unsigned)y1 < DH;
        s_w[c][0] = (bx0 && by0) ? w00 : 0.f;
        s_w[c][1] = (bx1 && by0) ? w01 : 0.f;
        s_w[c][2] = (bx0 && by1) ? w10 : 0.f;
        s_w[c][3] = (bx1 && by1) ? w11 : 0.f;
        int xc0 = min(max(x0,0),DW-1), xc1 = min(max(x1,0),DW-1);
        int yc0 = min(max(y0,0),DH-1), yc1 = min(max(y1,0),DH-1);
        unsigned cb = (unsigned)ci * (DH*DW*DD);
        s_addr[c][0] = cb + (yc0*DW + xc0)*DD;
        s_addr[c][1] = cb + (yc0*DW + xc1)*DD;
        s_addr[c][2] = cb + (yc1*DW + xc0)*DD;
        s_addr[c][3] = cb + (yc1*DW + xc1)*DD;
    }
    __syncthreads();

    // async gather: 8 cams x 4 corners x 64 chunks of 16B
    for (int i = tid; i < DC*4*64; i += 128) {
        int c = i >> 8;
        if (!s_vm[c]) continue;
        int r  = (i >> 6) & 3;
        int ch = i & 63;
        uint32_t dst = sb_data + (uint32_t)(((c*4 + r)*DD + ch*4) * 4);
        cpa16(dst, feat + (size_t)s_addr[c][r] + ch*4);
    }
    asm volatile("cp.async.commit_group;");

    // overlap: load qt slice + qbk while gather lands
    int t2 = tid*2;
    float2 qt = *(const float2*)(g_qt + (size_t)gw*DD + t2);
    float qb = g_qbk[gw];

    asm volatile("cp.async.wait_group 0;");
    __syncthreads();

    // blend + per-thread score partials
    float2 bl[DC];
    float  p[DC];
#pragma unroll
    for (int c = 0; c < DC; c++) {
        bl[c] = make_float2(0.f, 0.f);
        p[c] = 0.f;
        if (!s_vm[c]) continue;
        const float* dc = sdata + c*4*DD + t2;
        float2 v0 = *(const float2*)(dc);
        float2 v1 = *(const float2*)(dc + DD);
        float2 v2 = *(const float2*)(dc + 2*DD);
        float2 v3 = *(const float2*)(dc + 3*DD);
        float w0 = s_w[c][0], w1 = s_w[c][1], w2 = s_w[c][2], w3 = s_w[c][3];
        bl[c].x = w0*v0.x + w1*v1.x + w2*v2.x + w3*v3.x;
        bl[c].y = w0*v0.y + w1*v1.y + w2*v2.y + w3*v3.y;
        p[c] = bl[c].x*qt.x + bl[c].y*qt.y;
    }

    int lane = tid & 31, wd = tid >> 5;
#pragma unroll
    for (int c = 0; c < DC; c++) {
        if (!s_vm[c]) continue;
        float v = p[c];
#pragma unroll
        for (int off = 16; off; off >>= 1) v += __shfl_xor_sync(0xffffffffu, v, off);
        if (lane == 0) s_red[wd*DC + c] = v;
    }
    __syncthreads();

    float sc[DC];
    float m = -INFINITY;
#pragma unroll
    for (int c = 0; c < DC; c++) {
        sc[c] = -INFINITY;
        if (s_vm[c]) {
            float t = s_red[c] + s_red[DC + c] + s_red[2*DC + c] + s_red[3*DC + c];
            sc[c] = (t + qb)*0.0625f;
            m = fmaxf(m, sc[c]);
        }
    }

    float2 o = make_float2(0.f, 0.f);
    float Asum = 0.f;
    if (m != -INFINITY) {
        float w[DC], es = 0.f;
#pragma unroll
        for (int c = 0; c < DC; c++) {
            w[c] = 0.f;
            if (s_vm[c]) { w[c] = expf(sc[c] - m); es += w[c]; }
        }
        float r = 1.f/es;
#pragma unroll
        for (int c = 0; c < DC; c++) {
            if (!s_vm[c]) continue;
            float at = w[c]*r;
            Asum += at;
            o.x += at*bl[c].x;
            o.y += at*bl[c].y;
        }
    }
    __nv_bfloat16 hx, lx, hy, ly;
    bsplit(o.x, hx, lx);
    bsplit(o.y, hy, ly);
    *(unsigned*)(g_sb_h + (size_t)gw*DD + t2) = pk(hx, hy);
    *(unsigned*)(g_sb_l + (size_t)gw*DD + t2) = pk(lx, ly);
    if (tid == 0) g_asum[gw] = Asum;
}

// ---------------- launch ----------------
extern "C" void kernel_launch(void* const* d_in, const int* in_sizes, int n_in,
                              void* d_out, int out_size)
{
    const float* queries = (const float*)d_in[0];
    const float* feat    = (const float*)d_in[1];
    const float* coords  = (const float*)d_in[2];
    const int*   valid   = (const int*)  d_in[3];
    const float* Wq      = (const float*)d_in[4];
    const float* bq      = (const float*)d_in[5];
    const float* Wkv     = (const float*)d_in[6];
    const float* bkv     = (const float*)d_in[7];
    const float* Wo      = (const float*)d_in[8];
    const float* bo      = (const float*)d_in[9];
    const float* gamma   = (const float*)d_in[10];
    const float* beta    = (const float*)d_in[11];
    float* out = (float*)d_out;

    cudaFuncSetAttribute(k_mma, cudaFuncAttributeMaxDynamicSharedMemorySize, SMEM_MMA);

    k_tr <<<dim3(8,8,4), dim3(32,8)>>>(Wq, Wo, Wkv);
    k_vec<<<3, 256>>>(bq, bkv, Wo);
    k_pre<<<dim3(32,2), 256>>>(Wkv);
    k_ln <<<ROWS/8, 256>>>(queries, gamma, beta);
    k_mma<<<dim3(2, ROWS/128), 256, SMEM_MMA>>>(2, nullptr, nullptr, nullptr);
    k_attn<<<ROWS, 128>>>(feat, coords, valid);
    k_mma<<<dim3(2, ROWS/128), 256, SMEM_MMA>>>(3, out, queries, bo);
}

// round 8
// speedup vs baseline: 1.3323x; 1.3323x over previous
#include <cuda_runtime.h>
#include <cuda_bf16.h>
#include <math.h>
#include <stdint.h>

#define DB 2
#define DC 8
#define DN 16384
#define DD 256
#define DH 64
#define DW 64
#define ROWS (DB*DN)

// ---------------- scratch ----------------
__device__ __align__(256) __nv_bfloat16 g_qn_h [ROWS*DD];
__device__ __align__(256) __nv_bfloat16 g_qn_l [ROWS*DD];
__device__ __align__(256) float         g_qt   [ROWS*DD];
__device__ __align__(256) __nv_bfloat16 g_sb_h [ROWS*DD];
__device__ __align__(256) __nv_bfloat16 g_sb_l [ROWS*DD];
__device__ float g_qbk [ROWS];
__device__ float g_asum[ROWS];
__device__ __align__(256) float g_WqT [DD*DD];
__device__ __align__(256) float g_WoT [DD*DD];
__device__ __align__(256) float g_WvT [DD*DD];
__device__ __align__(256) float g_WkT [DD*DD];
__device__ __align__(256) __nv_bfloat16 g_MT_h [DD*DD];
__device__ __align__(256) __nv_bfloat16 g_MT_l [DD*DD];
__device__ __align__(256) __nv_bfloat16 g_W2T_h[DD*DD];
__device__ __align__(256) __nv_bfloat16 g_W2T_l[DD*DD];
__device__ float g_v1 [DD];
__device__ float g_u  [DD];
__device__ float g_wb2[DD];
__device__ float g_c0;

__device__ __forceinline__ float4 ld4(const float* p) { return *(const float4*)p; }

__device__ __forceinline__ void bsplit(float x, __nv_bfloat16& h, __nv_bfloat16& l) {
    h = __float2bfloat16_rn(x);
    l = __float2bfloat16_rn(x - __bfloat162float(h));
}
__device__ __forceinline__ unsigned pk(__nv_bfloat16 a, __nv_bfloat16 b) {
    unsigned short x = *(unsigned short*)&a, y = *(unsigned short*)&b;
    return (unsigned)x | ((unsigned)y << 16);
}

__device__ __forceinline__ uint32_t smem_u32(const void* p) {
    uint32_t a;
    asm("{ .reg .u64 t; cvta.to.shared.u64 t, %1; cvt.u32.u64 %0, t; }" : "=r"(a) : "l"(p));
    return a;
}
__device__ __forceinline__ void cpa16(uint32_t d, const void* s) {
    asm volatile("cp.async.cg.shared.global [%0], [%1], 16;" :: "r"(d), "l"(s));
}

#define LDM4(r, addr) \
    asm volatile("ldmatrix.sync.aligned.m8n8.x4.shared.b16 {%0,%1,%2,%3}, [%4];" \
        : "=r"((r)[0]), "=r"((r)[1]), "=r"((r)[2]), "=r"((r)[3]) : "r"(addr))

#define MMAB(d, a, b0, b1) \
    asm volatile("mma.sync.aligned.m16n8k16.row.col.f32.bf16.bf16.f32 " \
        "{%0,%1,%2,%3}, {%4,%5,%6,%7}, {%8,%9}, {%0,%1,%2,%3};" \
        : "+f"((d)[0]), "+f"((d)[1]), "+f"((d)[2]), "+f"((d)[3]) \
        : "r"((a)[0]), "r"((a)[1]), "r"((a)[2]), "r"((a)[3]), "r"(b0), "r"(b1))

// ---------------- transposes ----------------
__global__ void k_tr(const float* __restrict__ Wq, const float* __restrict__ Wo,
                     const float* __restrict__ Wkv)
{
    __shared__ float t[32][33];
    int z = blockIdx.z;
    const float* src; int ld, off; float* dst;
    if      (z == 0) { src = Wq;  ld = 256; off = 0;   dst = g_WqT; }
    else if (z == 1) { src = Wo;  ld = 256; off = 0;   dst = g_WoT; }
    else if (z == 2) { src = Wkv; ld = 512; off = 256; dst = g_WvT; }
    else             { src = Wkv; ld = 512; off = 0;   dst = g_WkT; }
    int bx = blockIdx.x*32, by = blockIdx.y*32;
    for (int yy = threadIdx.y; yy < 32; yy += 8)
        t[yy][threadIdx.x] = src[(size_t)(by+yy)*ld + off + bx + threadIdx.x];
    __syncthreads();
    for (int yy = threadIdx.y; yy < 32; yy += 8)
        dst[(size_t)(bx+yy)*256 + by + threadIdx.x] = t[threadIdx.x][yy];
}

// ---------------- small vectors ----------------
__global__ void k_vec(const float* __restrict__ bq, const float* __restrict__ bkv,
                      const float* __restrict__ Wo)
{
    int which = blockIdx.x, t = threadIdx.x;
    __shared__ float v[256];
    if      (which == 0) v[t] = bkv[t];
    else if (which == 1) v[t] = bq[t];
    else                 v[t] = bkv[256 + t];
    __syncthreads();
    float acc = 0.f;
    if (which == 0) {
        for (int d = 0; d < 256; d++) acc += g_WqT[d*256 + t] * v[d];
        g_u[t] = acc;
        if (t == 0) { float c = 0.f; for (int d = 0; d < 256; d++) c += bq[d]*bkv[d]; g_c0 = c; }
    } else if (which == 1) {
        for (int d = 0; d < 256; d++) acc += g_WkT[d*256 + t] * v[d];
        g_v1[t] = acc;
    } else {
        for (int f = 0; f < 256; f++) acc += Wo[f*256 + t] * v[f];
        g_wb2[t] = acc;
    }
}

// ---------------- MT[f][e] = Wk@Wq^T ; W2T[t][f] = (Wv@Wo)^T, emit bf16 hi/lo ----------------
__global__ __launch_bounds__(256) void k_pre(const float* __restrict__ Wkv)
{
    __shared__ float Ar[8][256];
    int r0 = blockIdx.x * 8;
    const float* Bsrc; __nv_bfloat16 *Ch, *Cl;
    if (blockIdx.y == 0) {
        for (int i = threadIdx.x; i < 8*256; i += 256) {
            int j = i >> 8, d = i & 255;
            Ar[j][d] = Wkv[(size_t)(r0+j)*512 + d];
        }
        Bsrc = g_WqT; Ch = g_MT_h; Cl = g_MT_l;
    } else {
        for (int i = threadIdx.x; i < 8*256; i += 256) {
            int j = i >> 8, d = i & 255;
            Ar[j][d] = g_WoT[(size_t)(r0+j)*256 + d];
        }
        Bsrc = g_WvT; Ch = g_W2T_h; Cl = g_W2T_l;
    }
    __syncthreads();
    int e = threadIdx.x;
    float acc[8];
#pragma unroll
    for (int j = 0; j < 8; j++) acc[j] = 0.f;
    for (int d = 0; d < 256; d++) {
        float b = Bsrc[(size_t)d*256 + e];
#pragma unroll
        for (int j = 0; j < 8; j++) acc[j] += Ar[j][d] * b;
    }
#pragma unroll
    for (int j = 0; j < 8; j++) {
        __nv_bfloat16 h, l; bsplit(acc[j], h, l);
        Ch[(size_t)(r0+j)*256 + e] = h;
        Cl[(size_t)(r0+j)*256 + e] = l;
    }
}

// ---------------- layernorm + qbk, emits bf16 hi/lo ----------------
__global__ __launch_bounds__(256) void k_ln(const float* __restrict__ q,
                                            const float* __restrict__ gamma,
                                            const float* __restrict__ beta)
{
    int gw   = (blockIdx.x*256 + threadIdx.x) >> 5;
    int lane = threadIdx.x & 31;
    const float* row = q + (size_t)gw*DD;
    float4 x0 = ld4(row + lane*4);
    float4 x1 = ld4(row + 128 + lane*4);
    float s  = x0.x+x0.y+x0.z+x0.w + x1.x+x1.y+x1.z+x1.w;
    float ss = x0.x*x0.x+x0.y*x0.y+x0.z*x0.z+x0.w*x0.w
             + x1.x*x1.x+x1.y*x1.y+x1.z*x1.z+x1.w*x1.w;
#pragma unroll
    for (int off = 16; off; off >>= 1) {
        s  += __shfl_xor_sync(0xffffffffu, s,  off);
        ss += __shfl_xor_sync(0xffffffffu, ss, off);
    }
    float mu   = s * (1.f/DD);
    float var  = ss * (1.f/DD) - mu*mu;
    float rstd = rsqrtf(var + 1e-5f);
    float4 gm0 = ld4(gamma + lane*4), gm1 = ld4(gamma + 128 + lane*4);
    float4 bt0 = ld4(beta  + lane*4), bt1 = ld4(beta  + 128 + lane*4);
    float y[8];
    y[0] = (x0.x-mu)*rstd*gm0.x + bt0.x;  y[1] = (x0.y-mu)*rstd*gm0.y + bt0.y;
    y[2] = (x0.z-mu)*rstd*gm0.z + bt0.z;  y[3] = (x0.w-mu)*rstd*gm0.w + bt0.w;
    y[4] = (x1.x-mu)*rstd*gm1.x + bt1.x;  y[5] = (x1.y-mu)*rstd*gm1.y + bt1.y;
    y[6] = (x1.z-mu)*rstd*gm1.z + bt1.z;  y[7] = (x1.w-mu)*rstd*gm1.w + bt1.w;

    __nv_bfloat16 h[8], l[8];
#pragma unroll
    for (int i = 0; i < 8; i++) bsplit(y[i], h[i], l[i]);
    size_t base = (size_t)gw*DD;
    *(uint2*)(g_qn_h + base + lane*4)       = make_uint2(pk(h[0],h[1]), pk(h[2],h[3]));
    *(uint2*)(g_qn_h + base + 128 + lane*4) = make_uint2(pk(h[4],h[5]), pk(h[6],h[7]));
    *(uint2*)(g_qn_l + base + lane*4)       = make_uint2(pk(l[0],l[1]), pk(l[2],l[3]));
    *(uint2*)(g_qn_l + base + 128 + lane*4) = make_uint2(pk(l[4],l[5]), pk(l[6],l[7]));

    float4 u0 = ld4(g_u + lane*4), u1 = ld4(g_u + 128 + lane*4);
    float p = y[0]*u0.x + y[1]*u0.y + y[2]*u0.z + y[3]*u0.w
            + y[4]*u1.x + y[5]*u1.y + y[6]*u1.z + y[7]*u1.w;
#pragma unroll
    for (int off = 16; off; off >>= 1) p += __shfl_xor_sync(0xffffffffu, p, off);
    if (lane == 0) g_qbk[gw] = p + g_c0;
}

// ================= bf16 3-split mma.sync GEMM with ldmatrix =================
// CTA 128x128, 8 warps (4x2), warp tile 32x64. K chunks of 32, 2-stage cp.async,
// 80 KB smem -> 2 CTAs/SM.
#define NCH 8
#define RS 80
#define ARR_B 10240
#define STG_BYTES (4*ARR_B)
#define SMEM_MMA (2*STG_BYTES)

__device__ __forceinline__ void ld_stage(uint32_t base,
        const __nv_bfloat16* __restrict__ Ah, const __nv_bfloat16* __restrict__ Al,
        const __nv_bfloat16* __restrict__ Bh, const __nv_bfloat16* __restrict__ Bl,
        size_t m0, int n0, int kb, int tid)
{
    for (int i = tid; i < 512; i += 256) {
        int row = i >> 2, slot = i & 3;
        uint32_t off = row*RS + slot*16;
        size_t ga = (m0 + row)*256 + kb + slot*8;
        size_t gb = (size_t)(n0 + row)*256 + kb + slot*8;
        cpa16(base + off,           Ah + ga);
        cpa16(base + ARR_B + off,   Al + ga);
        cpa16(base + 2*ARR_B + off, Bh + gb);
        cpa16(base + 3*ARR_B + off, Bl + gb);
    }
    asm volatile("cp.async.commit_group;");
}

__global__ __launch_bounds__(256, 2) void k_mma(int mode, float* __restrict__ outp,
                                                const float* __restrict__ resid,
                                                const float* __restrict__ bo)
{
    const __nv_bfloat16 *Ah, *Al, *Bh, *Bl; float* C;
    if (mode == 2) { Ah = g_qn_h; Al = g_qn_l; Bh = g_MT_h;  Bl = g_MT_l;  C = g_qt; }
    else           { Ah = g_sb_h; Al = g_sb_l; Bh = g_W2T_h; Bl = g_W2T_l; C = outp; }

    extern __shared__ __align__(16) char smem[];
    uint32_t sb = smem_u32(smem);
    int tid = threadIdx.x, lane = tid & 31, wid = tid >> 5;
    int wm = wid >> 1, wn = wid & 1;
    int qr = lane >> 2, qc = lane & 3;
    size_t m0 = (size_t)blockIdx.y * 128;
    int n0 = blockIdx.x * 128;

    uint32_t offA[2][2], offB[4][2];
    {
        int arow = lane & 15, asel = lane >> 4;
        int brow = (lane & 7) + ((lane & 16) >> 1);
        int bsel = (lane >> 3) & 1;
#pragma unroll
        for (int ks = 0; ks < 2; ks++) {
#pragma unroll
            for (int mi = 0; mi < 2; mi++)
                offA[mi][ks] = (uint32_t)((wm*32 + mi*16 + arow)*RS + (2*ks + asel)*16);
#pragma unroll
            for (int nip = 0; nip < 4; nip++)
                offB[nip][ks] = (uint32_t)((wn*64 + nip*16 + brow)*RS + (2*ks + bsel)*16);
        }
    }

    float acc[2][8][4];
#pragma unroll
    for (int mi = 0; mi < 2; mi++)
#pragma unroll
        for (int ni = 0; ni < 8; ni++)
#pragma unroll
            for (int t = 0; t < 4; t++) acc[mi][ni][t] = 0.f;

    ld_stage(sb, Ah, Al, Bh, Bl, m0, n0, 0, tid);

    for (int s = 0; s < NCH; s++) {
        if (s + 1 < NCH) {
            ld_stage(sb + ((s + 1) & 1)*STG_BYTES, Ah, Al, Bh, Bl, m0, n0, (s + 1)*32, tid);
            asm volatile("cp.async.wait_group 1;");
        } else {
            asm volatile("cp.async.wait_group 0;");
        }
        __syncthreads();

        uint32_t st = sb + (s & 1)*STG_BYTES;
#pragma unroll
        for (int ks = 0; ks < 2; ks++) {
            unsigned ra[2][4], la[2][4], rb[4][4], lb[4][4];
#pragma unroll
            for (int mi = 0; mi < 2; mi++) {
                LDM4(ra[mi], st + offA[mi][ks]);
                LDM4(la[mi], st + ARR_B + offA[mi][ks]);
            }
#pragma unroll
            for (int nip = 0; nip < 4; nip++) {
                LDM4(rb[nip], st + 2*ARR_B + offB[nip][ks]);
                LDM4(lb[nip], st + 3*ARR_B + offB[nip][ks]);
            }
#pragma unroll
            for (int mi = 0; mi < 2; mi++)
#pragma unroll
                for (int ni = 0; ni < 8; ni++)
                    MMAB(acc[mi][ni], ra[mi], rb[ni>>1][(ni&1)*2], rb[ni>>1][(ni&1)*2+1]);
#pragma unroll
            for (int mi = 0; mi < 2; mi++)
#pragma unroll
                for (int ni = 0; ni < 8; ni++)
                    MMAB(acc[mi][ni], ra[mi], lb[ni>>1][(ni&1)*2], lb[ni>>1][(ni&1)*2+1]);
#pragma unroll
            for (int mi = 0; mi < 2; mi++)
#pragma unroll
                for (int ni = 0; ni < 8; ni++)
                    MMAB(acc[mi][ni], la[mi], rb[ni>>1][(ni&1)*2], rb[ni>>1][(ni&1)*2+1]);
        }
        __syncthreads();
    }

#pragma unroll
    for (int mi = 0; mi < 2; mi++) {
        size_t r0 = m0 + wm*32 + mi*16 + qr;
        size_t r1 = r0 + 8;
        float as0 = 0.f, as1 = 0.f;
        if (mode == 3) { as0 = g_asum[r0]; as1 = g_asum[r1]; }
#pragma unroll
        for (int ni = 0; ni < 8; ni++) {
            int c = n0 + wn*64 + ni*8 + qc*2;
            float2 v0 = make_float2(acc[mi][ni][0], acc[mi][ni][1]);
            float2 v1 = make_float2(acc[mi][ni][2], acc[mi][ni][3]);
            if (mode == 2) {
                v0.x += g_v1[c]; v0.y += g_v1[c+1];
                v1.x += g_v1[c]; v1.y += g_v1[c+1];
            } else {
                float2 rs0 = *(const float2*)&resid[r0*256 + c];
                float2 rs1 = *(const float2*)&resid[r1*256 + c];
                float w0 = g_wb2[c], w1 = g_wb2[c+1];
                float b0 = bo[c], b1 = bo[c+1];
                v0.x += rs0.x + as0*w0 + b0;  v0.y += rs0.y + as0*w1 + b1;
                v1.x += rs1.x + as1*w0 + b0;  v1.y += rs1.y + as1*w1 + b1;
            }
            *(float2*)&C[r0*256 + c] = v0;
            *(float2*)&C[r1*256 + c] = v1;
        }
    }
}

// ---------------- fused bilinear gather + scores + softmax + weighted sum (R6) ----------------
__global__ __launch_bounds__(256) void k_attn(const float* __restrict__ feat,
                                              const float* __restrict__ coords,
                                              const int*   __restrict__ valid)
{
    int gw   = (blockIdx.x*256 + threadIdx.x) >> 5;
    int lane = threadIdx.x & 31;
    int b = gw >> 14;
    int n = gw & (DN - 1);

    const float* qtp = g_qt + (size_t)gw*DD;
    float4 qt0 = ld4(qtp + lane*4);
    float4 qt1 = ld4(qtp + 128 + lane*4);

    int vm[DC];
#pragma unroll
    for (int c = 0; c < DC; c++)
        vm[c] = valid[(size_t)(b*DC + c)*DN + n];

    float4 a0[DC], a1[DC];
    float  sc[DC];

#pragma unroll
    for (int c = 0; c < DC; c++) {
        sc[c] = -INFINITY;
        if (!vm[c]) continue;          // warp-uniform skip
        int ci = b*DC + c;
        float2 xy = *((const float2*)coords + (size_t)ci*DN + n);
        float x = (xy.x + 1.0f)*0.5f*(float)(DW - 1);
        float y = (xy.y + 1.0f)*0.5f*(float)(DH - 1);
        float x0f = floorf(x), y0f = floorf(y);
        float wx = x - x0f,    wy = y - y0f;
        int x0 = (int)x0f, y0 = (int)y0f;
        int x1 = x0 + 1,   y1 = y0 + 1;
        float w00 = (1.f-wy)*(1.f-wx), w01 = (1.f-wy)*wx;
        float w10 = wy*(1.f-wx),       w11 = wy*wx;
        bool bx0 = (unsigned)x0 < DW, bx1 = (unsigned)x1 < DW;
        bool by0 = (unsigned)y0 < DH, by1 = (unsigned)y1 < DH;
        w00 = (bx0 && by0) ? w00 : 0.f;  w01 = (bx1 && by0) ? w01 : 0.f;
        w10 = (bx0 && by1) ? w10 : 0.f;  w11 = (bx1 && by1) ? w11 : 0.f;
        int xc0 = min(max(x0,0),DW-1), xc1 = min(max(x1,0),DW-1);
        int yc0 = min(max(y0,0),DH-1), yc1 = min(max(y1,0),DH-1);

        const float* base = feat + (size_t)ci*(DH*DW*DD) + lane*4;
        const float* p00 = base + (yc0*DW + xc0)*DD;
        const float* p01 = base + (yc0*DW + xc1)*DD;
        const float* p10 = base + (yc1*DW + xc0)*DD;
        const float* p11 = base + (yc1*DW + xc1)*DD;
        float4 f00 = ld4(p00),     f01 = ld4(p01),     f10 = ld4(p10),     f11 = ld4(p11);
        float4 g00 = ld4(p00+128), g01 = ld4(p01+128), g10 = ld4(p10+128), g11 = ld4(p11+128);

        float4 va, vb;
        va.x = w00*f00.x + w01*f01.x + w10*f10.x + w11*f11.x;
        va.y = w00*f00.y + w01*f01.y + w10*f10.y + w11*f11.y;
        va.z = w00*f00.z + w01*f01.z + w10*f10.z + w11*f11.z;
        va.w = w00*f00.w + w01*f01.w + w10*f10.w + w11*f11.w;
        vb.x = w00*g00.x + w01*g01.x + w10*g10.x + w11*g11.x;
        vb.y = w00*g00.y + w01*g01.y + w10*g10.y + w11*g11.y;
        vb.z = w00*g00.z + w01*g01.z + w10*g10.z + w11*g11.z;
        vb.w = w00*g00.w + w01*g01.w + w10*g10.w + w11*g11.w;
        a0[c] = va; a1[c] = vb;
        sc[c] = va.x*qt0.x + va.y*qt0.y + va.z*qt0.z + va.w*qt0.w
              + vb.x*qt1.x + vb.y*qt1.y + vb.z*qt1.z + vb.w*qt1.w;
    }

#pragma unroll
    for (int c = 0; c < DC; c++) {
        if (!vm[c]) continue;
#pragma unroll
        for (int off = 16; off; off >>= 1)
            sc[c] += __shfl_xor_sync(0xffffffffu, sc[c], off);
    }

    float qb = g_qbk[gw];
    float m = -INFINITY;
#pragma unroll
    for (int c = 0; c < DC; c++) {
        if (vm[c]) { sc[c] = (sc[c] + qb)*0.0625f; m = fmaxf(m, sc[c]); }
    }

    float4 s0 = make_float4(0.f,0.f,0.f,0.f), s1 = make_float4(0.f,0.f,0.f,0.f);
    float Asum = 0.f;
    if (m != -INFINITY) {
        float w[DC];
        float es = 0.f;
#pragma unroll
        for (int c = 0; c < DC; c++) {
            w[c] = 0.f;
            if (vm[c]) { w[c] = expf(sc[c] - m); es += w[c]; }
        }
        float r = 1.f/es;
#pragma unroll
        for (int c = 0; c < DC; c++) {
            if (!vm[c]) continue;
            float at = w[c]*r;
            Asum += at;
            s0.x += at*a0[c].x; s0.y += at*a0[c].y; s0.z += at*a0[c].z; s0.w += at*a0[c].w;
            s1.x += at*a1[c].x; s1.y += at*a1[c].y; s1.z += at*a1[c].z; s1.w += at*a1[c].w;
        }
    }
    float v[8] = {s0.x,s0.y,s0.z,s0.w,s1.x,s1.y,s1.z,s1.w};
    __nv_bfloat16 h[8], l[8];
#pragma unroll
    for (int i = 0; i < 8; i++) bsplit(v[i], h[i], l[i]);
    size_t base2 = (size_t)gw*DD;
    *(uint2*)(g_sb_h + base2 + lane*4)       = make_uint2(pk(h[0],h[1]), pk(h[2],h[3]));
    *(uint2*)(g_sb_h + base2 + 128 + lane*4) = make_uint2(pk(h[4],h[5]), pk(h[6],h[7]));
    *(uint2*)(g_sb_l + base2 + lane*4)       = make_uint2(pk(l[0],l[1]), pk(l[2],l[3]));
    *(uint2*)(g_sb_l + base2 + 128 + lane*4) = make_uint2(pk(l[4],l[5]), pk(l[6],l[7]));
    if (lane == 0) g_asum[gw] = Asum;
}

// ---------------- launch ----------------
extern "C" void kernel_launch(void* const* d_in, const int* in_sizes, int n_in,
                              void* d_out, int out_size)
{
    const float* queries = (const float*)d_in[0];
    const float* feat    = (const float*)d_in[1];
    const float* coords  = (const float*)d_in[2];
    const int*   valid   = (const int*)  d_in[3];
    const float* Wq      = (const float*)d_in[4];
    const float* bq      = (const float*)d_in[5];
    const float* Wkv     = (const float*)d_in[6];
    const float* bkv     = (const float*)d_in[7];
    const float* Wo      = (const float*)d_in[8];
    const float* bo      = (const float*)d_in[9];
    const float* gamma   = (const float*)d_in[10];
    const float* beta    = (const float*)d_in[11];
    float* out = (float*)d_out;

    cudaFuncSetAttribute(k_mma, cudaFuncAttributeMaxDynamicSharedMemorySize, SMEM_MMA);

    k_tr <<<dim3(8,8,4), dim3(32,8)>>>(Wq, Wo, Wkv);
    k_vec<<<3, 256>>>(bq, bkv, Wo);
    k_pre<<<dim3(32,2), 256>>>(Wkv);
    k_ln <<<ROWS/8, 256>>>(queries, gamma, beta);
    k_mma<<<dim3(2, ROWS/128), 256, SMEM_MMA>>>(2, nullptr, nullptr, nullptr);
    k_attn<<<ROWS/8, 256>>>(feat, coords, valid);
    k_mma<<<dim3(2, ROWS/128), 256, SMEM_MMA>>>(3, out, queries, bo);
}